// round 1
// baseline (speedup 1.0000x reference)
#include <cuda_runtime.h>
#include <math.h>
#include <stdint.h>

#define Nn   65536
#define Bg   64
#define NPG  1024
#define Ag   32
#define HIDN 128
#define Eg   262144
#define Lg   3
#define NEG  0.2f

// ---------------- scratch (device globals; no allocation allowed) ----------------
__device__ float g_h[Nn * HIDN];
__device__ float g_xl[Nn * HIDN];
__device__ float g_xr[Nn * HIDN];
__device__ int   g_indptr[Nn + 1];
__device__ int   g_cursor[Nn];
__device__ int   g_deg[Nn];
__device__ int   g_csr_src[Eg];
__device__ float g_csr_ea[Eg];
__device__ float g_partial[256];
__device__ float g_ea_mean;
__device__ float g_pool_sum[Bg * HIDN];
__device__ float g_pool_max[Bg * HIDN];

// ---------------- packed f32x2 helpers (sm_103a FFMA2) ----------------
__device__ __forceinline__ unsigned long long pack2(float lo, float hi) {
    unsigned long long r;
    asm("mov.b64 %0, {%1, %2};" : "=l"(r) : "f"(lo), "f"(hi));
    return r;
}
__device__ __forceinline__ void ffma2(unsigned long long& d, unsigned long long a, unsigned long long b) {
    asm("fma.rn.f32x2 %0, %1, %2, %0;" : "+l"(d) : "l"(a), "l"(b));
}
__device__ __forceinline__ float2 unpack2(unsigned long long v) {
    float2 f;
    asm("mov.b64 {%0, %1}, %2;" : "=f"(f.x), "=f"(f.y) : "l"(v));
    return f;
}

// ---------------- small utility kernels ----------------
__global__ void k_zero() {
    int i = blockIdx.x * blockDim.x + threadIdx.x;
    if (i < Nn) g_deg[i] = 0;
    if (i < Bg * HIDN) { g_pool_sum[i] = 0.f; g_pool_max[i] = 0.f; }
}

__global__ void k_mean1(const float* __restrict__ ea) {
    __shared__ float red[256];
    float s = 0.f;
    for (int i = blockIdx.x * 256 + threadIdx.x; i < Eg; i += 256 * 256) s += ea[i];
    red[threadIdx.x] = s; __syncthreads();
    for (int st = 128; st > 0; st >>= 1) {
        if (threadIdx.x < st) red[threadIdx.x] += red[threadIdx.x + st];
        __syncthreads();
    }
    if (threadIdx.x == 0) g_partial[blockIdx.x] = red[0];
}

__global__ void k_mean2() {
    __shared__ float red[256];
    red[threadIdx.x] = g_partial[threadIdx.x]; __syncthreads();
    for (int st = 128; st > 0; st >>= 1) {
        if (threadIdx.x < st) red[threadIdx.x] += red[threadIdx.x + st];
        __syncthreads();
    }
    if (threadIdx.x == 0) g_ea_mean = red[0] / (float)Eg;
}

__global__ void k_hist(const int* __restrict__ ei) {
    int e = blockIdx.x * blockDim.x + threadIdx.x;
    if (e < Eg) atomicAdd(&g_deg[ei[Eg + e]], 1);
}

__global__ __launch_bounds__(1024) void k_scan() {
    __shared__ int ssum[1024];
    int t = threadIdx.x;
    int base = t * 64;
    int s = 0;
    #pragma unroll 8
    for (int i = 0; i < 64; i++) s += g_deg[base + i];
    ssum[t] = s; __syncthreads();
    for (int off = 1; off < 1024; off <<= 1) {
        int v = (t >= off) ? ssum[t - off] : 0;
        __syncthreads();
        ssum[t] += v;
        __syncthreads();
    }
    int run = (t == 0) ? 0 : ssum[t - 1];
    for (int i = 0; i < 64; i++) {
        g_indptr[base + i] = run;
        g_cursor[base + i] = run;
        run += g_deg[base + i];
    }
    if (t == 1023) g_indptr[Nn] = run;
}

__global__ void k_fill(const int* __restrict__ ei, const float* __restrict__ ea) {
    int e = blockIdx.x * blockDim.x + threadIdx.x;
    if (e < Eg) {
        int d = ei[Eg + e];
        int pos = atomicAdd(&g_cursor[d], 1);
        g_csr_src[pos] = ei[e];
        g_csr_ea[pos]  = ea[e];
    }
}

__global__ void k_inith(const float* __restrict__ x, const float* __restrict__ Wn,
                        const float* __restrict__ bn) {
    int idx = blockIdx.x * blockDim.x + threadIdx.x;   // Nn*32 threads
    int node = idx >> 5;
    int c = (idx & 31) << 2;
    float xv = x[node];
    float4 w = *(const float4*)(Wn + c);
    float4 b = *(const float4*)(bn + c);
    float4 o;
    o.x = fmaxf(fmaf(xv, w.x, b.x), 0.f);
    o.y = fmaxf(fmaf(xv, w.y, b.y), 0.f);
    o.z = fmaxf(fmaf(xv, w.z, b.z), 0.f);
    o.w = fmaxf(fmaf(xv, w.w, b.w), 0.f);
    *(float4*)(g_h + node * HIDN + c) = o;
}

// ---------------- dual GEMM: xl = h@W1+b1, xr = h@W2+b2 ----------------
// tile: 64 rows x 256 cols, 256 threads, thread = 4 rows x 8 col-pairs (FFMA2)
__global__ __launch_bounds__(256) void k_gemm_dual(const float* __restrict__ W1,
                                                   const float* __restrict__ W2,
                                                   const float* __restrict__ b1,
                                                   const float* __restrict__ b2) {
    extern __shared__ float sm[];
    float* sA = sm;              // 64 x 132 (padded)
    float* sW = sm + 64 * 132;   // 128 x 256
    const int tid  = threadIdx.x;
    const int row0 = blockIdx.x * 64;

    for (int i = tid; i < 64 * 32; i += 256) {
        int r = i >> 5, c = (i & 31) << 2;
        *(float4*)(sA + r * 132 + c) = *(const float4*)(g_h + (row0 + r) * HIDN + c);
    }
    for (int i = tid; i < 128 * 32; i += 256) {
        int k = i >> 5, c = (i & 31) << 2;
        *(float4*)(sW + k * 256 + c)       = *(const float4*)(W1 + k * HIDN + c);
        *(float4*)(sW + k * 256 + 128 + c) = *(const float4*)(W2 + k * HIDN + c);
    }
    __syncthreads();

    const int tx = tid & 15, ty = tid >> 4;
    unsigned long long acc[4][8];
    #pragma unroll
    for (int r = 0; r < 4; r++)
        #pragma unroll
        for (int p = 0; p < 8; p++) acc[r][p] = 0ull;

    const float* pA = sA + ty * 4 * 132;
    const float* pW = sW + tx * 2;     // pair columns: c = tx*2 + p*32

    #pragma unroll 2
    for (int k = 0; k < 128; k++) {
        unsigned long long av[4];
        #pragma unroll
        for (int r = 0; r < 4; r++) { float a = pA[r * 132 + k]; av[r] = pack2(a, a); }
        unsigned long long wv[8];
        #pragma unroll
        for (int p = 0; p < 8; p++)
            wv[p] = *(const unsigned long long*)(pW + (size_t)k * 256 + p * 32);
        #pragma unroll
        for (int r = 0; r < 4; r++)
            #pragma unroll
            for (int p = 0; p < 8; p++) ffma2(acc[r][p], av[r], wv[p]);
    }

    #pragma unroll
    for (int p = 0; p < 8; p++) {
        int c = tx * 2 + p * 32;              // 0..254
        const float* bb = (c < 128) ? b1 : b2;
        float* outp     = (c < 128) ? g_xl : g_xr;
        int cc = c & 127;
        float2 bv = *(const float2*)(bb + cc);
        #pragma unroll
        for (int r = 0; r < 4; r++) {
            float2 v = unpack2(acc[r][p]);
            v.x += bv.x; v.y += bv.y;
            *(float2*)(outp + (size_t)(row0 + ty * 4 + r) * HIDN + cc) = v;
        }
    }
}

// ---------------- edge aggregation: one warp per node, online softmax ----------------
__global__ __launch_bounds__(256) void k_edge(const float* __restrict__ We,
                                              const float* __restrict__ att,
                                              const float* __restrict__ gb) {
    int warp = (blockIdx.x * blockDim.x + threadIdx.x) >> 5;
    int lane = threadIdx.x & 31;
    if (warp >= Nn) return;
    const int i = warp;

    float wv[4], av[4], xr_[4], xls[4], hold[4];
    #pragma unroll
    for (int r = 0; r < 4; r++) {
        int j = r * 32 + lane;
        wv[r]   = We[j];
        av[r]   = att[j];
        xr_[r]  = g_xr[(size_t)i * HIDN + j];
        xls[r]  = g_xl[(size_t)i * HIDN + j];
        hold[r] = g_h[(size_t)i * HIDN + j];
    }
    float eam = g_ea_mean;

    float m[4], s[4], acc[4];
    #pragma unroll
    for (int r = 0; r < 4; r++) {
        float t = fmaf(eam, wv[r], xls[r] + xr_[r]);
        t = (t > 0.f) ? t : NEG * t;
        float p = t * av[r];
        #pragma unroll
        for (int o = 16; o > 0; o >>= 1) p += __shfl_xor_sync(0xffffffffu, p, o);
        m[r] = p; s[r] = 1.f; acc[r] = xls[r];
    }

    int e0 = g_indptr[i], e1 = g_indptr[i + 1];
    for (int e = e0; e < e1; e++) {
        int   src = g_csr_src[e];
        float a   = g_csr_ea[e];
        float xs[4], lg[4];
        #pragma unroll
        for (int r = 0; r < 4; r++) {
            int j = r * 32 + lane;
            xs[r] = g_xl[(size_t)src * HIDN + j];
            float t = fmaf(a, wv[r], xs[r] + xr_[r]);
            t = (t > 0.f) ? t : NEG * t;
            float p = t * av[r];
            #pragma unroll
            for (int o = 16; o > 0; o >>= 1) p += __shfl_xor_sync(0xffffffffu, p, o);
            lg[r] = p;
        }
        #pragma unroll
        for (int r = 0; r < 4; r++) {
            float mn = fmaxf(m[r], lg[r]);
            float sc = __expf(m[r] - mn);
            float p  = __expf(lg[r] - mn);
            s[r]   = fmaf(s[r], sc, p);
            acc[r] = fmaf(acc[r], sc, p * xs[r]);
            m[r]   = mn;
        }
    }

    #pragma unroll
    for (int r = 0; r < 4; r++) {
        float o = acc[r] / s[r] + gb[r * 32 + lane];
        g_h[(size_t)i * HIDN + r * 32 + lane] = fmaxf(o, 0.f) + hold[r];
    }
}

// ---------------- pooling (h >= 0, so int-bit atomicMax is valid) ----------------
__global__ void k_pool() {
    int b = blockIdx.x >> 3;
    int chunk = blockIdx.x & 7;
    int j = threadIdx.x;
    int node0 = b * NPG + chunk * 128;
    float s = 0.f, mx = 0.f;
    #pragma unroll 4
    for (int t = 0; t < 128; t++) {
        float v = g_h[(size_t)(node0 + t) * HIDN + j];
        s += v;
        mx = fmaxf(mx, v);
    }
    atomicAdd(&g_pool_sum[b * HIDN + j], s);
    atomicMax((int*)&g_pool_max[b * HIDN + j], __float_as_int(mx));
}

// ---------------- fused action encoder + Q head: block = (graph, 16 actions) ----------------
__global__ __launch_bounds__(256) void k_head(const float* __restrict__ at,
        const float* __restrict__ aW1, const float* __restrict__ ab1,
        const float* __restrict__ aW2, const float* __restrict__ ab2,
        const float* __restrict__ qW1, const float* __restrict__ qb1,
        const float* __restrict__ qW2, const float* __restrict__ qb2,
        const float* __restrict__ qW3, const float* __restrict__ qb3,
        float* __restrict__ out) {
    extern __shared__ float sm[];
    float* IN   = sm;                 // 16 x 516
    float* S1   = IN + 16 * 516;      // 16 x 128
    float* S2   = S1 + 16 * 128;      // 16 x 128
    float* tcol = S2 + 16 * 128;      // 128
    float* ps   = tcol + 128;         // 128
    float* pm   = ps + 128;           // 128

    const int tid = threadIdx.x;
    const int b   = blockIdx.x >> 1;
    const int a0  = (blockIdx.x & 1) * 16;

    if (tid < 128) {
        ps[tid] = g_pool_sum[b * HIDN + tid];
        pm[tid] = g_pool_max[b * HIDN + tid];
    }
    __syncthreads();

    // gather action inputs
    for (int idx = tid; idx < 16 * 512; idx += 256) {
        int a = idx >> 9, q = idx & 511;
        int slot = q >> 7, col = q & 127;
        int node = (int)at[(size_t)(b * Ag + a0 + a) * 7 + slot] + b * NPG;
        IN[a * 516 + q] = g_h[(size_t)node * HIDN + col];
    }
    for (int idx = tid; idx < 16 * 3; idx += 256) {
        int a = idx / 3, ms = idx % 3;
        IN[a * 516 + 512 + ms] = at[(size_t)(b * Ag + a0 + a) * 7 + 4 + ms];
    }
    // tree_emb @ qW1[0:384] (per-block constant part of q1)
    if (tid < 128) {
        float acc = qb1[tid];
        for (int k = 0; k < 128; k++) {
            float sv = ps[k];
            acc = fmaf(sv, qW1[k * 128 + tid], acc);
            acc = fmaf(sv * (1.f / 1024.f), qW1[(128 + k) * 128 + tid], acc);
            acc = fmaf(pm[k], qW1[(256 + k) * 128 + tid], acc);
        }
        tcol[tid] = acc;
    }
    __syncthreads();

    const int col = tid & 127;
    const int ab  = (tid >> 7) * 8;

    // MLP1: 515 -> 128
    {
        float acc[8]; float bias = ab1[col];
        #pragma unroll
        for (int a = 0; a < 8; a++) acc[a] = bias;
        for (int k = 0; k < 515; k++) {
            float w = aW1[k * 128 + col];
            #pragma unroll
            for (int a = 0; a < 8; a++) acc[a] = fmaf(IN[(ab + a) * 516 + k], w, acc[a]);
        }
        #pragma unroll
        for (int a = 0; a < 8; a++) S1[(ab + a) * 128 + col] = fmaxf(acc[a], 0.f);
    }
    __syncthreads();
    // MLP2: 128 -> 128
    {
        float acc[8]; float bias = ab2[col];
        #pragma unroll
        for (int a = 0; a < 8; a++) acc[a] = bias;
        for (int k = 0; k < 128; k++) {
            float w = aW2[k * 128 + col];
            #pragma unroll
            for (int a = 0; a < 8; a++) acc[a] = fmaf(S1[(ab + a) * 128 + k], w, acc[a]);
        }
        #pragma unroll
        for (int a = 0; a < 8; a++) S2[(ab + a) * 128 + col] = fmaxf(acc[a], 0.f);
    }
    __syncthreads();
    // q1 = relu(tcol + ae @ qW1[384:512])
    {
        float acc[8]; float t = tcol[col];
        #pragma unroll
        for (int a = 0; a < 8; a++) acc[a] = t;
        for (int k = 0; k < 128; k++) {
            float w = qW1[(384 + k) * 128 + col];
            #pragma unroll
            for (int a = 0; a < 8; a++) acc[a] = fmaf(S2[(ab + a) * 128 + k], w, acc[a]);
        }
        #pragma unroll
        for (int a = 0; a < 8; a++) S1[(ab + a) * 128 + col] = fmaxf(acc[a], 0.f);
    }
    __syncthreads();
    // q2
    {
        float acc[8]; float bias = qb2[col];
        #pragma unroll
        for (int a = 0; a < 8; a++) acc[a] = bias;
        for (int k = 0; k < 128; k++) {
            float w = qW2[k * 128 + col];
            #pragma unroll
            for (int a = 0; a < 8; a++) acc[a] = fmaf(S1[(ab + a) * 128 + k], w, acc[a]);
        }
        #pragma unroll
        for (int a = 0; a < 8; a++) S2[(ab + a) * 128 + col] = fmaxf(acc[a], 0.f);
    }
    __syncthreads();
    // final dot with qW3
    {
        int w_id = tid >> 5, lane = tid & 31;
        for (int a = w_id; a < 16; a += 8) {
            float s = 0.f;
            #pragma unroll
            for (int kk = 0; kk < 4; kk++)
                s = fmaf(S2[a * 128 + kk * 32 + lane], qW3[kk * 32 + lane], s);
            #pragma unroll
            for (int o = 16; o > 0; o >>= 1) s += __shfl_xor_sync(0xffffffffu, s, o);
            if (lane == 0) out[b * Ag + a0 + a] = s + qb3[0];
        }
    }
}

// ---------------- launch ----------------
extern "C" void kernel_launch(void* const* d_in, const int* in_sizes, int n_in,
                              void* d_out, int out_size) {
    const float *x, *edge_attr, *action_tensor;
    const float *Wn, *bn, *gWl, *gbl, *gWr, *gbr, *gWe, *gatt, *gb;
    const float *aW1, *ab1, *aW2, *ab2, *qW1, *qb1, *qW2, *qb2, *qW3, *qb3;
    const int* edge_index;

    x             = (const float*)d_in[0];
    edge_attr     = (const float*)d_in[1];
    action_tensor = (const float*)d_in[2];

    if (in_sizes[3] > 100000) {     // dict-insertion order: edge_index at [3]
        edge_index = (const int*)d_in[3];
        Wn  = (const float*)d_in[6];  bn  = (const float*)d_in[7];
        gWl = (const float*)d_in[8];  gWr = (const float*)d_in[9];
        gWe = (const float*)d_in[10]; gatt= (const float*)d_in[11];
        gbl = (const float*)d_in[12]; gbr = (const float*)d_in[13];
        gb  = (const float*)d_in[14];
        aW1 = (const float*)d_in[15]; ab1 = (const float*)d_in[16];
        aW2 = (const float*)d_in[17]; ab2 = (const float*)d_in[18];
        qW1 = (const float*)d_in[19]; qb1 = (const float*)d_in[20];
        qW2 = (const float*)d_in[21]; qb2 = (const float*)d_in[22];
        qW3 = (const float*)d_in[23]; qb3 = (const float*)d_in[24];
    } else {                         // reference-signature order
        Wn  = (const float*)d_in[3];  bn  = (const float*)d_in[4];
        gWl = (const float*)d_in[5];  gbl = (const float*)d_in[6];
        gWr = (const float*)d_in[7];  gbr = (const float*)d_in[8];
        gWe = (const float*)d_in[9];  gatt= (const float*)d_in[10];
        gb  = (const float*)d_in[11];
        aW1 = (const float*)d_in[12]; ab1 = (const float*)d_in[13];
        aW2 = (const float*)d_in[14]; ab2 = (const float*)d_in[15];
        qW1 = (const float*)d_in[16]; qb1 = (const float*)d_in[17];
        qW2 = (const float*)d_in[18]; qb2 = (const float*)d_in[19];
        qW3 = (const float*)d_in[20]; qb3 = (const float*)d_in[21];
        edge_index = (const int*)d_in[22];
    }

    const int SMEM_G = (64 * 132 + 128 * 256) * 4;                    // 164864
    const int SMEM_H = (16 * 516 + 2 * 16 * 128 + 3 * 128) * 4;      // 50944
    cudaFuncSetAttribute(k_gemm_dual, cudaFuncAttributeMaxDynamicSharedMemorySize, SMEM_G);
    cudaFuncSetAttribute(k_head,      cudaFuncAttributeMaxDynamicSharedMemorySize, SMEM_H);

    k_zero<<<Nn / 256, 256>>>();
    k_mean1<<<256, 256>>>(edge_attr);
    k_mean2<<<1, 256>>>();
    k_hist<<<Eg / 256, 256>>>(edge_index);
    k_scan<<<1, 1024>>>();
    k_fill<<<Eg / 256, 256>>>(edge_index, edge_attr);
    k_inith<<<Nn * 32 / 256, 256>>>(x, Wn, bn);

    for (int l = 0; l < Lg; l++) {
        k_gemm_dual<<<Nn / 64, 256, SMEM_G>>>(gWl + l * HIDN * HIDN, gWr + l * HIDN * HIDN,
                                              gbl + l * HIDN, gbr + l * HIDN);
        k_edge<<<Nn / 8, 256>>>(gWe + l * HIDN, gatt + l * HIDN, gb + l * HIDN);
    }

    k_pool<<<Bg * 8, 128>>>();
    k_head<<<Bg * 2, 256, SMEM_H>>>(action_tensor, aW1, ab1, aW2, ab2,
                                    qW1, qb1, qW2, qb2, qW3, qb3, (float*)d_out);
}

// round 2
// speedup vs baseline: 1.0920x; 1.0920x over previous
#include <cuda_runtime.h>
#include <math.h>
#include <stdint.h>

#define Nn   65536
#define Bg   64
#define NPG  1024
#define Ag   32
#define HIDN 128
#define Eg   262144
#define Lg   3
#define NEG  0.2f

// ---------------- scratch (device globals; no allocation allowed) ----------------
__device__ float g_h[Nn * HIDN];
__device__ float g_xl[Nn * HIDN];
__device__ float g_xr[Nn * HIDN];
__device__ int   g_indptr[Nn + 1];
__device__ int   g_cursor[Nn];
__device__ int   g_deg[Nn];
__device__ int   g_csr_src[Eg];
__device__ float g_csr_ea[Eg];
__device__ float g_partial[1024];
__device__ float g_ea_mean;
__device__ float g_pool_sum[Bg * HIDN];
__device__ float g_pool_max[Bg * HIDN];

// ---------------- packed f32x2 helpers (sm_103a FFMA2) ----------------
__device__ __forceinline__ unsigned long long pack2(float lo, float hi) {
    unsigned long long r;
    asm("mov.b64 %0, {%1, %2};" : "=l"(r) : "f"(lo), "f"(hi));
    return r;
}
__device__ __forceinline__ void ffma2(unsigned long long& d, unsigned long long a, unsigned long long b) {
    asm("fma.rn.f32x2 %0, %1, %2, %0;" : "+l"(d) : "l"(a), "l"(b));
}
__device__ __forceinline__ float2 unpack2(unsigned long long v) {
    float2 f;
    asm("mov.b64 {%0, %1}, %2;" : "=f"(f.x), "=f"(f.y) : "l"(v));
    return f;
}

// ---------------- launch 1: zero counters ----------------
__global__ void k_zero() {
    int i = blockIdx.x * blockDim.x + threadIdx.x;
    if (i < Nn) g_deg[i] = 0;
    if (i < Bg * HIDN) { g_pool_sum[i] = 0.f; g_pool_max[i] = 0.f; }
}

// ---------------- launch 2: h0 = relu(x @ Wn + bn), NF = 1 ----------------
__global__ void k_inith(const float* __restrict__ x, const float* __restrict__ Wn,
                        const float* __restrict__ bn) {
    int idx = blockIdx.x * blockDim.x + threadIdx.x;   // Nn*32 threads
    int node = idx >> 5;
    int c = (idx & 31) << 2;
    float xv = x[node];
    float4 w = *(const float4*)(Wn + c);
    float4 b = *(const float4*)(bn + c);
    float4 o;
    o.x = fmaxf(fmaf(xv, w.x, b.x), 0.f);
    o.y = fmaxf(fmaf(xv, w.y, b.y), 0.f);
    o.z = fmaxf(fmaf(xv, w.z, b.z), 0.f);
    o.w = fmaxf(fmaf(xv, w.w, b.w), 0.f);
    *(float4*)(g_h + node * HIDN + c) = o;
}

// ---------------- launch 3: degree histogram + edge_attr mean partials ----------------
__global__ void k_hist(const int* __restrict__ ei, const float* __restrict__ ea) {
    __shared__ float red[256];
    int e = blockIdx.x * 256 + threadIdx.x;      // grid = 1024 blocks, exactly Eg threads
    atomicAdd(&g_deg[ei[Eg + e]], 1);
    red[threadIdx.x] = ea[e];
    __syncthreads();
    for (int st = 128; st > 0; st >>= 1) {
        if (threadIdx.x < st) red[threadIdx.x] += red[threadIdx.x + st];
        __syncthreads();
    }
    if (threadIdx.x == 0) g_partial[blockIdx.x] = red[0];
}

// ---------------- launch 4: dual GEMM  xl = h@W1+b1, xr = h@W2+b2 ----------------
// tile: 128 rows x 256 cols, 512 threads, thread = 4 rows x 8 col-pairs (FFMA2)
__global__ __launch_bounds__(512) void k_gemm_dual(const float* __restrict__ W1,
                                                   const float* __restrict__ W2,
                                                   const float* __restrict__ b1,
                                                   const float* __restrict__ b2) {
    extern __shared__ float sm[];
    float* sA = sm;               // 128 x 132 (padded)
    float* sW = sm + 128 * 132;   // 128 x 256
    const int tid  = threadIdx.x;
    const int row0 = blockIdx.x * 128;

    for (int i = tid; i < 128 * 32; i += 512) {
        int r = i >> 5, c = (i & 31) << 2;
        *(float4*)(sA + r * 132 + c) = *(const float4*)(g_h + (size_t)(row0 + r) * HIDN + c);
        *(float4*)(sW + r * 256 + c)       = *(const float4*)(W1 + r * HIDN + c);
        *(float4*)(sW + r * 256 + 128 + c) = *(const float4*)(W2 + r * HIDN + c);
    }
    __syncthreads();

    const int tx = tid & 15, ty = tid >> 4;      // ty: 0..31 -> rows ty*4..ty*4+3
    unsigned long long acc[4][8];
    #pragma unroll
    for (int r = 0; r < 4; r++)
        #pragma unroll
        for (int p = 0; p < 8; p++) acc[r][p] = 0ull;

    const float* pA = sA + ty * 4 * 132;
    const float* pW = sW + tx * 2;               // pair columns: c = tx*2 + p*32

    #pragma unroll 1
    for (int k = 0; k < 128; k++) {
        unsigned long long av[4];
        #pragma unroll
        for (int r = 0; r < 4; r++) { float a = pA[r * 132 + k]; av[r] = pack2(a, a); }
        unsigned long long wv[8];
        #pragma unroll
        for (int p = 0; p < 8; p++)
            wv[p] = *(const unsigned long long*)(pW + (size_t)k * 256 + p * 32);
        #pragma unroll
        for (int r = 0; r < 4; r++)
            #pragma unroll
            for (int p = 0; p < 8; p++) ffma2(acc[r][p], av[r], wv[p]);
    }

    #pragma unroll
    for (int p = 0; p < 8; p++) {
        int c = tx * 2 + p * 32;                 // 0..254
        const float* bb = (c < 128) ? b1 : b2;
        float* outp     = (c < 128) ? g_xl : g_xr;
        int cc = c & 127;
        float2 bv = *(const float2*)(bb + cc);
        #pragma unroll
        for (int r = 0; r < 4; r++) {
            float2 v = unpack2(acc[r][p]);
            v.x += bv.x; v.y += bv.y;
            *(float2*)(outp + (size_t)(row0 + ty * 4 + r) * HIDN + cc) = v;
        }
    }
}

// ---------------- launch 5: exclusive scan of degrees + finish edge_attr mean ----------------
__global__ __launch_bounds__(1024) void k_scan() {
    __shared__ int   ssum[1024];
    __shared__ float fred[1024];
    int t = threadIdx.x;

    fred[t] = g_partial[t];
    int base = t * 64;
    int s = 0;
    #pragma unroll 8
    for (int i = 0; i < 64; i++) s += g_deg[base + i];
    ssum[t] = s; __syncthreads();
    for (int off = 1; off < 1024; off <<= 1) {
        int v = (t >= off) ? ssum[t - off] : 0;
        __syncthreads();
        ssum[t] += v;
        __syncthreads();
    }
    int run = (t == 0) ? 0 : ssum[t - 1];
    for (int i = 0; i < 64; i++) {
        g_indptr[base + i] = run;
        g_cursor[base + i] = run;
        run += g_deg[base + i];
    }
    if (t == 1023) g_indptr[Nn] = run;

    // mean finalize
    for (int st = 512; st > 0; st >>= 1) {
        __syncthreads();
        if (t < st) fred[t] += fred[t + st];
    }
    __syncthreads();
    if (t == 0) g_ea_mean = fred[0] / (float)Eg;
}

// ---------------- launch 6: CSR fill ----------------
__global__ void k_fill(const int* __restrict__ ei, const float* __restrict__ ea) {
    int e = blockIdx.x * blockDim.x + threadIdx.x;
    if (e < Eg) {
        int d = ei[Eg + e];
        int pos = atomicAdd(&g_cursor[d], 1);
        g_csr_src[pos] = ei[e];
        g_csr_ea[pos]  = ea[e];
    }
}

// ---------------- edge aggregation: one warp per node, online softmax, unroll-2 ----------------
__global__ __launch_bounds__(256) void k_edge(const float* __restrict__ We,
                                              const float* __restrict__ att,
                                              const float* __restrict__ gb) {
    int warp = (blockIdx.x * blockDim.x + threadIdx.x) >> 5;
    int lane = threadIdx.x & 31;
    if (warp >= Nn) return;
    const int i = warp;

    float wv[4], av[4], xr_[4], xls[4], hold[4];
    #pragma unroll
    for (int r = 0; r < 4; r++) {
        int j = r * 32 + lane;
        wv[r]   = We[j];
        av[r]   = att[j];
        xr_[r]  = g_xr[(size_t)i * HIDN + j];
        xls[r]  = g_xl[(size_t)i * HIDN + j];
        hold[r] = g_h[(size_t)i * HIDN + j];
    }
    float eam = g_ea_mean;

    // self-loop initializes online softmax state
    float m[4], s[4], acc[4];
    {
        float p[4];
        #pragma unroll
        for (int r = 0; r < 4; r++) {
            float t = fmaf(eam, wv[r], xls[r] + xr_[r]);
            t = (t > 0.f) ? t : NEG * t;
            p[r] = t * av[r];
        }
        #pragma unroll
        for (int o = 16; o > 0; o >>= 1) {
            #pragma unroll
            for (int r = 0; r < 4; r++) p[r] += __shfl_xor_sync(0xffffffffu, p[r], o);
        }
        #pragma unroll
        for (int r = 0; r < 4; r++) { m[r] = p[r]; s[r] = 1.f; acc[r] = xls[r]; }
    }

    int e0 = g_indptr[i], e1 = g_indptr[i + 1];
    int e = e0;
    for (; e + 2 <= e1; e += 2) {
        int   src0 = g_csr_src[e],     src1 = g_csr_src[e + 1];
        float a0   = g_csr_ea[e],      a1   = g_csr_ea[e + 1];
        float xs0[4], xs1[4], q0[4], q1[4];
        #pragma unroll
        for (int r = 0; r < 4; r++) {
            int j = r * 32 + lane;
            xs0[r] = __ldg(&g_xl[(size_t)src0 * HIDN + j]);
            xs1[r] = __ldg(&g_xl[(size_t)src1 * HIDN + j]);
        }
        #pragma unroll
        for (int r = 0; r < 4; r++) {
            float t0 = fmaf(a0, wv[r], xs0[r] + xr_[r]);
            t0 = (t0 > 0.f) ? t0 : NEG * t0;
            q0[r] = t0 * av[r];
            float t1 = fmaf(a1, wv[r], xs1[r] + xr_[r]);
            t1 = (t1 > 0.f) ? t1 : NEG * t1;
            q1[r] = t1 * av[r];
        }
        // 8 independent butterfly chains interleaved
        #pragma unroll
        for (int o = 16; o > 0; o >>= 1) {
            #pragma unroll
            for (int r = 0; r < 4; r++) {
                q0[r] += __shfl_xor_sync(0xffffffffu, q0[r], o);
                q1[r] += __shfl_xor_sync(0xffffffffu, q1[r], o);
            }
        }
        #pragma unroll
        for (int r = 0; r < 4; r++) {
            float mn = fmaxf(m[r], fmaxf(q0[r], q1[r]));
            float sc = __expf(m[r] - mn);
            float p0 = __expf(q0[r] - mn);
            float p1 = __expf(q1[r] - mn);
            s[r]   = fmaf(s[r], sc, p0 + p1);
            acc[r] = fmaf(acc[r], sc, fmaf(p0, xs0[r], p1 * xs1[r]));
            m[r]   = mn;
        }
    }
    if (e < e1) {
        int   src = g_csr_src[e];
        float a   = g_csr_ea[e];
        float xs[4], q[4];
        #pragma unroll
        for (int r = 0; r < 4; r++) {
            int j = r * 32 + lane;
            xs[r] = __ldg(&g_xl[(size_t)src * HIDN + j]);
            float t = fmaf(a, wv[r], xs[r] + xr_[r]);
            t = (t > 0.f) ? t : NEG * t;
            q[r] = t * av[r];
        }
        #pragma unroll
        for (int o = 16; o > 0; o >>= 1) {
            #pragma unroll
            for (int r = 0; r < 4; r++) q[r] += __shfl_xor_sync(0xffffffffu, q[r], o);
        }
        #pragma unroll
        for (int r = 0; r < 4; r++) {
            float mn = fmaxf(m[r], q[r]);
            float sc = __expf(m[r] - mn);
            float p  = __expf(q[r] - mn);
            s[r]   = fmaf(s[r], sc, p);
            acc[r] = fmaf(acc[r], sc, p * xs[r]);
            m[r]   = mn;
        }
    }

    #pragma unroll
    for (int r = 0; r < 4; r++) {
        float o = acc[r] / s[r] + gb[r * 32 + lane];
        g_h[(size_t)i * HIDN + r * 32 + lane] = fmaxf(o, 0.f) + hold[r];
    }
}

// ---------------- pooling (h >= 0, so int-bit atomicMax is valid) ----------------
__global__ void k_pool() {
    int b = blockIdx.x >> 3;
    int chunk = blockIdx.x & 7;
    int j = threadIdx.x;
    int node0 = b * NPG + chunk * 128;
    float s = 0.f, mx = 0.f;
    #pragma unroll 4
    for (int t = 0; t < 128; t++) {
        float v = g_h[(size_t)(node0 + t) * HIDN + j];
        s += v;
        mx = fmaxf(mx, v);
    }
    atomicAdd(&g_pool_sum[b * HIDN + j], s);
    atomicMax((int*)&g_pool_max[b * HIDN + j], __float_as_int(mx));
}

// ---------------- fused action encoder + Q head: block = (graph, 16 actions) ----------------
__global__ __launch_bounds__(256) void k_head(const float* __restrict__ at,
        const float* __restrict__ aW1, const float* __restrict__ ab1,
        const float* __restrict__ aW2, const float* __restrict__ ab2,
        const float* __restrict__ qW1, const float* __restrict__ qb1,
        const float* __restrict__ qW2, const float* __restrict__ qb2,
        const float* __restrict__ qW3, const float* __restrict__ qb3,
        float* __restrict__ out) {
    extern __shared__ float sm[];
    float* IN   = sm;                 // 16 x 516
    float* S1   = IN + 16 * 516;      // 16 x 128
    float* S2   = S1 + 16 * 128;      // 16 x 128
    float* tcol = S2 + 16 * 128;      // 128
    float* ps   = tcol + 128;         // 128
    float* pm   = ps + 128;           // 128

    const int tid = threadIdx.x;
    const int b   = blockIdx.x >> 1;
    const int a0  = (blockIdx.x & 1) * 16;

    if (tid < 128) {
        ps[tid] = g_pool_sum[b * HIDN + tid];
        pm[tid] = g_pool_max[b * HIDN + tid];
    }
    __syncthreads();

    for (int idx = tid; idx < 16 * 512; idx += 256) {
        int a = idx >> 9, q = idx & 511;
        int slot = q >> 7, col = q & 127;
        int node = (int)at[(size_t)(b * Ag + a0 + a) * 7 + slot] + b * NPG;
        IN[a * 516 + q] = g_h[(size_t)node * HIDN + col];
    }
    for (int idx = tid; idx < 16 * 3; idx += 256) {
        int a = idx / 3, ms = idx % 3;
        IN[a * 516 + 512 + ms] = at[(size_t)(b * Ag + a0 + a) * 7 + 4 + ms];
    }
    if (tid < 128) {
        float acc = qb1[tid];
        for (int k = 0; k < 128; k++) {
            float sv = ps[k];
            acc = fmaf(sv, qW1[k * 128 + tid], acc);
            acc = fmaf(sv * (1.f / 1024.f), qW1[(128 + k) * 128 + tid], acc);
            acc = fmaf(pm[k], qW1[(256 + k) * 128 + tid], acc);
        }
        tcol[tid] = acc;
    }
    __syncthreads();

    const int col = tid & 127;
    const int ab  = (tid >> 7) * 8;

    {
        float acc[8]; float bias = ab1[col];
        #pragma unroll
        for (int a = 0; a < 8; a++) acc[a] = bias;
        for (int k = 0; k < 515; k++) {
            float w = aW1[k * 128 + col];
            #pragma unroll
            for (int a = 0; a < 8; a++) acc[a] = fmaf(IN[(ab + a) * 516 + k], w, acc[a]);
        }
        #pragma unroll
        for (int a = 0; a < 8; a++) S1[(ab + a) * 128 + col] = fmaxf(acc[a], 0.f);
    }
    __syncthreads();
    {
        float acc[8]; float bias = ab2[col];
        #pragma unroll
        for (int a = 0; a < 8; a++) acc[a] = bias;
        for (int k = 0; k < 128; k++) {
            float w = aW2[k * 128 + col];
            #pragma unroll
            for (int a = 0; a < 8; a++) acc[a] = fmaf(S1[(ab + a) * 128 + k], w, acc[a]);
        }
        #pragma unroll
        for (int a = 0; a < 8; a++) S2[(ab + a) * 128 + col] = fmaxf(acc[a], 0.f);
    }
    __syncthreads();
    {
        float acc[8]; float t = tcol[col];
        #pragma unroll
        for (int a = 0; a < 8; a++) acc[a] = t;
        for (int k = 0; k < 128; k++) {
            float w = qW1[(384 + k) * 128 + col];
            #pragma unroll
            for (int a = 0; a < 8; a++) acc[a] = fmaf(S2[(ab + a) * 128 + k], w, acc[a]);
        }
        #pragma unroll
        for (int a = 0; a < 8; a++) S1[(ab + a) * 128 + col] = fmaxf(acc[a], 0.f);
    }
    __syncthreads();
    {
        float acc[8]; float bias = qb2[col];
        #pragma unroll
        for (int a = 0; a < 8; a++) acc[a] = bias;
        for (int k = 0; k < 128; k++) {
            float w = qW2[k * 128 + col];
            #pragma unroll
            for (int a = 0; a < 8; a++) acc[a] = fmaf(S1[(ab + a) * 128 + k], w, acc[a]);
        }
        #pragma unroll
        for (int a = 0; a < 8; a++) S2[(ab + a) * 128 + col] = fmaxf(acc[a], 0.f);
    }
    __syncthreads();
    {
        int w_id = tid >> 5, lane = tid & 31;
        for (int a = w_id; a < 16; a += 8) {
            float s = 0.f;
            #pragma unroll
            for (int kk = 0; kk < 4; kk++)
                s = fmaf(S2[a * 128 + kk * 32 + lane], qW3[kk * 32 + lane], s);
            #pragma unroll
            for (int o = 16; o > 0; o >>= 1) s += __shfl_xor_sync(0xffffffffu, s, o);
            if (lane == 0) out[b * Ag + a0 + a] = s + qb3[0];
        }
    }
}

// ---------------- launch ----------------
extern "C" void kernel_launch(void* const* d_in, const int* in_sizes, int n_in,
                              void* d_out, int out_size) {
    const float *x, *edge_attr, *action_tensor;
    const float *Wn, *bn, *gWl, *gbl, *gWr, *gbr, *gWe, *gatt, *gb;
    const float *aW1, *ab1, *aW2, *ab2, *qW1, *qb1, *qW2, *qb2, *qW3, *qb3;
    const int* edge_index;

    x             = (const float*)d_in[0];
    edge_attr     = (const float*)d_in[1];
    action_tensor = (const float*)d_in[2];

    if (in_sizes[3] > 100000) {
        edge_index = (const int*)d_in[3];
        Wn  = (const float*)d_in[6];  bn  = (const float*)d_in[7];
        gWl = (const float*)d_in[8];  gWr = (const float*)d_in[9];
        gWe = (const float*)d_in[10]; gatt= (const float*)d_in[11];
        gbl = (const float*)d_in[12]; gbr = (const float*)d_in[13];
        gb  = (const float*)d_in[14];
        aW1 = (const float*)d_in[15]; ab1 = (const float*)d_in[16];
        aW2 = (const float*)d_in[17]; ab2 = (const float*)d_in[18];
        qW1 = (const float*)d_in[19]; qb1 = (const float*)d_in[20];
        qW2 = (const float*)d_in[21]; qb2 = (const float*)d_in[22];
        qW3 = (const float*)d_in[23]; qb3 = (const float*)d_in[24];
    } else {
        Wn  = (const float*)d_in[3];  bn  = (const float*)d_in[4];
        gWl = (const float*)d_in[5];  gbl = (const float*)d_in[6];
        gWr = (const float*)d_in[7];  gbr = (const float*)d_in[8];
        gWe = (const float*)d_in[9];  gatt= (const float*)d_in[10];
        gb  = (const float*)d_in[11];
        aW1 = (const float*)d_in[12]; ab1 = (const float*)d_in[13];
        aW2 = (const float*)d_in[14]; ab2 = (const float*)d_in[15];
        qW1 = (const float*)d_in[16]; qb1 = (const float*)d_in[17];
        qW2 = (const float*)d_in[18]; qb2 = (const float*)d_in[19];
        qW3 = (const float*)d_in[20]; qb3 = (const float*)d_in[21];
        edge_index = (const int*)d_in[22];
    }

    const int SMEM_G = (128 * 132 + 128 * 256) * 4;                   // 198656
    const int SMEM_H = (16 * 516 + 2 * 16 * 128 + 3 * 128) * 4;       // 50944
    cudaFuncSetAttribute(k_gemm_dual, cudaFuncAttributeMaxDynamicSharedMemorySize, SMEM_G);
    cudaFuncSetAttribute(k_head,      cudaFuncAttributeMaxDynamicSharedMemorySize, SMEM_H);

    // launch order positions k_gemm_dual at launch #4 (where ncu's window landed last round)
    k_zero<<<Nn / 256, 256>>>();                                   // 1
    k_inith<<<Nn * 32 / 256, 256>>>(x, Wn, bn);                    // 2
    k_hist<<<Eg / 256, 256>>>(edge_index, edge_attr);              // 3
    k_gemm_dual<<<Nn / 128, 512, SMEM_G>>>(gWl, gWr, gbl, gbr);    // 4  <- ncu capture target
    k_scan<<<1, 1024>>>();                                         // 5
    k_fill<<<Eg / 256, 256>>>(edge_index, edge_attr);              // 6
    k_edge<<<Nn / 8, 256>>>(gWe, gatt, gb);                        // 7

    for (int l = 1; l < Lg; l++) {
        k_gemm_dual<<<Nn / 128, 512, SMEM_G>>>(gWl + l * HIDN * HIDN, gWr + l * HIDN * HIDN,
                                               gbl + l * HIDN, gbr + l * HIDN);
        k_edge<<<Nn / 8, 256>>>(gWe + l * HIDN, gatt + l * HIDN, gb + l * HIDN);
    }

    k_pool<<<Bg * 8, 128>>>();
    k_head<<<Bg * 2, 256, SMEM_H>>>(action_tensor, aW1, ab1, aW2, ab2,
                                    qW1, qb1, qW2, qb2, qW3, qb3, (float*)d_out);
}